// round 12
// baseline (speedup 1.0000x reference)
#include <cuda_runtime.h>

// MovementEmbeddingModule: bs=4, d=16, K=10, C=3, h=w=128
// out: (bs, K*6, d, h, w) float32
// R10 body (two aligned LDG.128 per channel-row, templated uniform shift,
// rolling prefiltered rows, next-row prefetch, __stcs STG.128) with finer
// block granularity (RPW=4, 5120 blocks) to shrink the last-wave tail.
// (Resubmission of R11 — previous round died to a container infra failure.)

#define WIDTH  128
#define HEIGHT 128
#define KNUM   10
#define DNUM   16
#define CNUM   3
#define BSNUM  4
#define RPW    4    // rows per warp

template <int N> struct IC { static constexpr int value = N; };

__global__ __launch_bounds__(128) void movement_kernel(
    const float* __restrict__ kp_app,   // (4,1,10,2)
    const float* __restrict__ kp_vid,   // (4,16,10,2)
    const float* __restrict__ img,      // (4,3,1,128,128)
    float* __restrict__ out)            // (4,60,16,128,128)
{
    const int bdk = blockIdx.x;             // 0..639
    const int k   = bdk % KNUM;
    const int t   = bdk / KNUM;
    const int dd  = t % DNUM;
    const int b   = t / DNUM;

    const float2 kva = *(const float2*)(kp_app + (b * KNUM + k) * 2);
    const float2 kv  = *(const float2*)(kp_vid + ((b * DNUM + dd) * KNUM + k) * 2);
    const float2 kv0 = *(const float2*)(kp_vid + ((b * DNUM + 0)  * KNUM + k) * 2);

    const float diffx = kv.x - kv0.x;
    const float diffy = kv.y - kv0.y;
    const float mx = diffx + kva.x;
    const float my = diffy + kva.y;
    const float vdx = -diffx;
    const float vdy = -diffy;

    const int lane = threadIdx.x & 31;
    const int warp = threadIdx.x >> 5;      // 0..3
    const int x0   = lane * 4;
    const int ybase = blockIdx.y * (4 * RPW) + warp * RPW;

    // ---- constant bilinear weights + integer shift (x) ----
    const float xi0 = vdx * 63.5f;
    const float fx  = floorf(xi0);
    const float wx1 = xi0 - fx;
    const float wx0 = 1.0f - wx1;
    const int   ixb = (int)fx;              // corner col for output x=0
    const int   s   = ixb & 3;              // uniform per block

    // two aligned float4 blocks covering this lane's 5-tap window
    const int blk0 = (ixb >> 2) + lane;
    const int bic0 = min(max(blk0,     0), WIDTH / 4 - 1);
    const int bic1 = min(max(blk0 + 1, 0), WIDTH / 4 - 1);

    // per-pixel masked x-weights (zero any OOB tap; clamped loads are finite)
    float mw0[4], mw1[4];
    #pragma unroll
    for (int i = 0; i < 4; ++i) {
        const int ci0 = ixb + x0 + i, ci1 = ci0 + 1;
        mw0[i] = (ci0 >= 0 && ci0 < WIDTH) ? wx0 : 0.0f;
        mw1[i] = (ci1 >= 0 && ci1 < WIDTH) ? wx1 : 0.0f;
    }

    // ---- constant weights + shift (y) ----
    const float yi0 = vdy * 63.5f;
    const float fy  = floorf(yi0);
    const float wy1 = yi0 - fy;
    const float wy0 = 1.0f - wy1;
    const int   iyb = (int)fy;

    // ---- factored heatmap x-terms ----
    float exd[4], ex0[4];
    #pragma unroll
    for (int i = 0; i < 4; ++i) {
        const float gx = fmaf((float)(x0 + i), 2.0f / 127.0f, -1.0f);
        const float dm = gx - mx;    exd[i] = __expf(-50.0f * dm * dm);
        const float da = gx - kva.x; ex0[i] = __expf(-50.0f * da * da);
    }

    const float* imgb = img + (size_t)b * CNUM * HEIGHT * WIDTH;
    const int chStride = DNUM * HEIGHT * WIDTH;
    float* outb = out
        + ((size_t)(b * (KNUM * 6) + k * 6) * DNUM + dd) * (size_t)(HEIGHT * WIDTH)
        + x0;

    const float4 vdx4 = make_float4(vdx, vdx, vdx, vdx);
    const float4 vdy4 = make_float4(vdy, vdy, vdy, vdy);

    auto run = [&](auto Sc) {
        constexpr int S = decltype(Sc)::value;

        // issue raw loads for one source row (3 channels)
        auto issue_loads = [&](int rowc, float4 (&a)[3], float4 (&c)[3]) {
            #pragma unroll
            for (int ch = 0; ch < 3; ++ch) {
                const float4* p = (const float4*)(imgb + ch * (HEIGHT * WIDTH) + rowc * WIDTH);
                a[ch] = __ldg(p + bic0);
                c[ch] = __ldg(p + bic1);
            }
        };

        // horizontal prefilter from raw pair
        auto hfilter = [&](const float4 (&a)[3], const float4 (&c)[3], float (&h)[3][4]) {
            #pragma unroll
            for (int ch = 0; ch < 3; ++ch) {
                const float w8[8] = {a[ch].x, a[ch].y, a[ch].z, a[ch].w,
                                     c[ch].x, c[ch].y, c[ch].z, c[ch].w};
                float v[5];
                #pragma unroll
                for (int j = 0; j < 5; ++j) v[j] = w8[S + j];   // static select
                #pragma unroll
                for (int i = 0; i < 4; ++i)
                    h[ch][i] = mw0[i] * v[i] + mw1[i] * v[i + 1];
            }
        };

        float4 na[3], nc[3];         // in-flight next row
        float toph[3][4], both[3][4];

        // prime: top row for r=0
        issue_loads(min(max(iyb + ybase, 0), HEIGHT - 1), na, nc);
        hfilter(na, nc, toph);
        // prefetch bottom row for r=0
        issue_loads(min(max(iyb + ybase + 1, 0), HEIGHT - 1), na, nc);

        #pragma unroll
        for (int r = 0; r < RPW; ++r) {
            const int y  = ybase + r;
            const int rt = iyb + y;
            const int rb = rt + 1;
            const float wyt = (rt >= 0 && rt < HEIGHT) ? wy0 : 0.0f;
            const float wyb = (rb >= 0 && rb < HEIGHT) ? wy1 : 0.0f;

            // grab current raw row, then immediately issue next row's loads
            float4 ca[3], cc[3];
            #pragma unroll
            for (int ch = 0; ch < 3; ++ch) { ca[ch] = na[ch]; cc[ch] = nc[ch]; }
            if (r + 1 < RPW)
                issue_loads(min(max(rb + 1, 0), HEIGHT - 1), na, nc);

            hfilter(ca, cc, both);

            // heatmap (factored Gaussian)
            const float gy  = fmaf((float)y, 2.0f / 127.0f, -1.0f);
            const float dym = gy - my;    const float eyd = __expf(-50.0f * dym * dym);
            const float dya = gy - kva.y; const float eya = __expf(-50.0f * dya * dya);
            float4 hm;
            hm.x = eyd * exd[0] - eya * ex0[0];
            hm.y = eyd * exd[1] - eya * ex0[1];
            hm.z = eyd * exd[2] - eya * ex0[2];
            hm.w = eyd * exd[3] - eya * ex0[3];

            // vertical 2-tap on prefiltered rows
            float4 dv[3];
            #pragma unroll
            for (int ch = 0; ch < 3; ++ch) {
                dv[ch].x = wyt * toph[ch][0] + wyb * both[ch][0];
                dv[ch].y = wyt * toph[ch][1] + wyb * both[ch][1];
                dv[ch].z = wyt * toph[ch][2] + wyb * both[ch][2];
                dv[ch].w = wyt * toph[ch][3] + wyb * both[ch][3];
            }

            float* o = outb + y * WIDTH;
            __stcs((float4*)(o),                hm);
            __stcs((float4*)(o + chStride),     vdx4);
            __stcs((float4*)(o + 2 * chStride), vdy4);
            __stcs((float4*)(o + 3 * chStride), dv[0]);
            __stcs((float4*)(o + 4 * chStride), dv[1]);
            __stcs((float4*)(o + 5 * chStride), dv[2]);

            #pragma unroll
            for (int ch = 0; ch < 3; ++ch)
                #pragma unroll
                for (int i = 0; i < 4; ++i) toph[ch][i] = both[ch][i];
        }
    };

    switch (s) {
        case 0: run(IC<0>{}); break;
        case 1: run(IC<1>{}); break;
        case 2: run(IC<2>{}); break;
        default: run(IC<3>{}); break;
    }
}

extern "C" void kernel_launch(void* const* d_in, const int* in_sizes, int n_in,
                              void* d_out, int out_size) {
    const float* kp_app = nullptr;   // 80
    const float* kp_vid = nullptr;   // 1280
    const float* img    = nullptr;   // 196608
    for (int i = 0; i < n_in; ++i) {
        if (in_sizes[i] == BSNUM * 1 * KNUM * 2)               kp_app = (const float*)d_in[i];
        else if (in_sizes[i] == BSNUM * DNUM * KNUM * 2)       kp_vid = (const float*)d_in[i];
        else if (in_sizes[i] == BSNUM * CNUM * HEIGHT * WIDTH) img    = (const float*)d_in[i];
    }
    float* out = (float*)d_out;

    dim3 grid(BSNUM * DNUM * KNUM, HEIGHT / (4 * RPW), 1);   // 640 x 8
    dim3 block(128, 1, 1);
    movement_kernel<<<grid, block>>>(kp_app, kp_vid, img, out);
}

// round 13
// speedup vs baseline: 1.0925x; 1.0925x over previous
#include <cuda_runtime.h>

// MovementEmbeddingModule: bs=4, d=16, K=10, C=3, h=w=128
// out: (bs, K*6, d, h, w) float32
// R12 body (two aligned LDG.128 per channel-row, templated uniform shift,
// rolling prefiltered rows, next-row prefetch, __stcs STG.128, RPW=4) with
// swapped grid rasterization: consecutive blocks cover the 8 y-slabs of the
// SAME (b,d,k) so co-scheduled CTAs write the same contiguous channel
// streams (DRAM page locality).

#define WIDTH  128
#define HEIGHT 128
#define KNUM   10
#define DNUM   16
#define CNUM   3
#define BSNUM  4
#define RPW    4    // rows per warp

template <int N> struct IC { static constexpr int value = N; };

__global__ __launch_bounds__(128) void movement_kernel(
    const float* __restrict__ kp_app,   // (4,1,10,2)
    const float* __restrict__ kp_vid,   // (4,16,10,2)
    const float* __restrict__ img,      // (4,3,1,128,128)
    float* __restrict__ out)            // (4,60,16,128,128)
{
    const int bdk = blockIdx.y;             // 0..639  (slow dim now)
    const int k   = bdk % KNUM;
    const int t   = bdk / KNUM;
    const int dd  = t % DNUM;
    const int b   = t / DNUM;

    const float2 kva = *(const float2*)(kp_app + (b * KNUM + k) * 2);
    const float2 kv  = *(const float2*)(kp_vid + ((b * DNUM + dd) * KNUM + k) * 2);
    const float2 kv0 = *(const float2*)(kp_vid + ((b * DNUM + 0)  * KNUM + k) * 2);

    const float diffx = kv.x - kv0.x;
    const float diffy = kv.y - kv0.y;
    const float mx = diffx + kva.x;
    const float my = diffy + kva.y;
    const float vdx = -diffx;
    const float vdy = -diffy;

    const int lane = threadIdx.x & 31;
    const int warp = threadIdx.x >> 5;      // 0..3
    const int x0   = lane * 4;
    const int ybase = blockIdx.x * (4 * RPW) + warp * RPW;   // fast dim = y-slab

    // ---- constant bilinear weights + integer shift (x) ----
    const float xi0 = vdx * 63.5f;
    const float fx  = floorf(xi0);
    const float wx1 = xi0 - fx;
    const float wx0 = 1.0f - wx1;
    const int   ixb = (int)fx;              // corner col for output x=0
    const int   s   = ixb & 3;              // uniform per block

    // two aligned float4 blocks covering this lane's 5-tap window
    const int blk0 = (ixb >> 2) + lane;
    const int bic0 = min(max(blk0,     0), WIDTH / 4 - 1);
    const int bic1 = min(max(blk0 + 1, 0), WIDTH / 4 - 1);

    // per-pixel masked x-weights (zero any OOB tap; clamped loads are finite)
    float mw0[4], mw1[4];
    #pragma unroll
    for (int i = 0; i < 4; ++i) {
        const int ci0 = ixb + x0 + i, ci1 = ci0 + 1;
        mw0[i] = (ci0 >= 0 && ci0 < WIDTH) ? wx0 : 0.0f;
        mw1[i] = (ci1 >= 0 && ci1 < WIDTH) ? wx1 : 0.0f;
    }

    // ---- constant weights + shift (y) ----
    const float yi0 = vdy * 63.5f;
    const float fy  = floorf(yi0);
    const float wy1 = yi0 - fy;
    const float wy0 = 1.0f - wy1;
    const int   iyb = (int)fy;

    // ---- factored heatmap x-terms ----
    float exd[4], ex0[4];
    #pragma unroll
    for (int i = 0; i < 4; ++i) {
        const float gx = fmaf((float)(x0 + i), 2.0f / 127.0f, -1.0f);
        const float dm = gx - mx;    exd[i] = __expf(-50.0f * dm * dm);
        const float da = gx - kva.x; ex0[i] = __expf(-50.0f * da * da);
    }

    const float* imgb = img + (size_t)b * CNUM * HEIGHT * WIDTH;
    const int chStride = DNUM * HEIGHT * WIDTH;
    float* outb = out
        + ((size_t)(b * (KNUM * 6) + k * 6) * DNUM + dd) * (size_t)(HEIGHT * WIDTH)
        + x0;

    const float4 vdx4 = make_float4(vdx, vdx, vdx, vdx);
    const float4 vdy4 = make_float4(vdy, vdy, vdy, vdy);

    auto run = [&](auto Sc) {
        constexpr int S = decltype(Sc)::value;

        // issue raw loads for one source row (3 channels)
        auto issue_loads = [&](int rowc, float4 (&a)[3], float4 (&c)[3]) {
            #pragma unroll
            for (int ch = 0; ch < 3; ++ch) {
                const float4* p = (const float4*)(imgb + ch * (HEIGHT * WIDTH) + rowc * WIDTH);
                a[ch] = __ldg(p + bic0);
                c[ch] = __ldg(p + bic1);
            }
        };

        // horizontal prefilter from raw pair
        auto hfilter = [&](const float4 (&a)[3], const float4 (&c)[3], float (&h)[3][4]) {
            #pragma unroll
            for (int ch = 0; ch < 3; ++ch) {
                const float w8[8] = {a[ch].x, a[ch].y, a[ch].z, a[ch].w,
                                     c[ch].x, c[ch].y, c[ch].z, c[ch].w};
                float v[5];
                #pragma unroll
                for (int j = 0; j < 5; ++j) v[j] = w8[S + j];   // static select
                #pragma unroll
                for (int i = 0; i < 4; ++i)
                    h[ch][i] = mw0[i] * v[i] + mw1[i] * v[i + 1];
            }
        };

        float4 na[3], nc[3];         // in-flight next row
        float toph[3][4], both[3][4];

        // prime: top row for r=0
        issue_loads(min(max(iyb + ybase, 0), HEIGHT - 1), na, nc);
        hfilter(na, nc, toph);
        // prefetch bottom row for r=0
        issue_loads(min(max(iyb + ybase + 1, 0), HEIGHT - 1), na, nc);

        #pragma unroll
        for (int r = 0; r < RPW; ++r) {
            const int y  = ybase + r;
            const int rt = iyb + y;
            const int rb = rt + 1;
            const float wyt = (rt >= 0 && rt < HEIGHT) ? wy0 : 0.0f;
            const float wyb = (rb >= 0 && rb < HEIGHT) ? wy1 : 0.0f;

            // grab current raw row, then immediately issue next row's loads
            float4 ca[3], cc[3];
            #pragma unroll
            for (int ch = 0; ch < 3; ++ch) { ca[ch] = na[ch]; cc[ch] = nc[ch]; }
            if (r + 1 < RPW)
                issue_loads(min(max(rb + 1, 0), HEIGHT - 1), na, nc);

            hfilter(ca, cc, both);

            // heatmap (factored Gaussian)
            const float gy  = fmaf((float)y, 2.0f / 127.0f, -1.0f);
            const float dym = gy - my;    const float eyd = __expf(-50.0f * dym * dym);
            const float dya = gy - kva.y; const float eya = __expf(-50.0f * dya * dya);
            float4 hm;
            hm.x = eyd * exd[0] - eya * ex0[0];
            hm.y = eyd * exd[1] - eya * ex0[1];
            hm.z = eyd * exd[2] - eya * ex0[2];
            hm.w = eyd * exd[3] - eya * ex0[3];

            // vertical 2-tap on prefiltered rows
            float4 dv[3];
            #pragma unroll
            for (int ch = 0; ch < 3; ++ch) {
                dv[ch].x = wyt * toph[ch][0] + wyb * both[ch][0];
                dv[ch].y = wyt * toph[ch][1] + wyb * both[ch][1];
                dv[ch].z = wyt * toph[ch][2] + wyb * both[ch][2];
                dv[ch].w = wyt * toph[ch][3] + wyb * both[ch][3];
            }

            float* o = outb + y * WIDTH;
            __stcs((float4*)(o),                hm);
            __stcs((float4*)(o + chStride),     vdx4);
            __stcs((float4*)(o + 2 * chStride), vdy4);
            __stcs((float4*)(o + 3 * chStride), dv[0]);
            __stcs((float4*)(o + 4 * chStride), dv[1]);
            __stcs((float4*)(o + 5 * chStride), dv[2]);

            #pragma unroll
            for (int ch = 0; ch < 3; ++ch)
                #pragma unroll
                for (int i = 0; i < 4; ++i) toph[ch][i] = both[ch][i];
        }
    };

    switch (s) {
        case 0: run(IC<0>{}); break;
        case 1: run(IC<1>{}); break;
        case 2: run(IC<2>{}); break;
        default: run(IC<3>{}); break;
    }
}

extern "C" void kernel_launch(void* const* d_in, const int* in_sizes, int n_in,
                              void* d_out, int out_size) {
    const float* kp_app = nullptr;   // 80
    const float* kp_vid = nullptr;   // 1280
    const float* img    = nullptr;   // 196608
    for (int i = 0; i < n_in; ++i) {
        if (in_sizes[i] == BSNUM * 1 * KNUM * 2)               kp_app = (const float*)d_in[i];
        else if (in_sizes[i] == BSNUM * DNUM * KNUM * 2)       kp_vid = (const float*)d_in[i];
        else if (in_sizes[i] == BSNUM * CNUM * HEIGHT * WIDTH) img    = (const float*)d_in[i];
    }
    float* out = (float*)d_out;

    // fast dim = y-slabs of one (b,d,k); slow dim = bdk
    dim3 grid(HEIGHT / (4 * RPW), BSNUM * DNUM * KNUM, 1);   // 8 x 640
    dim3 block(128, 1, 1);
    movement_kernel<<<grid, block>>>(kp_app, kp_vid, img, out);
}